// round 5
// baseline (speedup 1.0000x reference)
#include <cuda_runtime.h>
#include <cuda_bf16.h>

// Gumbel-softmax palette quantization, fused single pass.
// probs = softmax((images + gumbel)/T, axis=k);  out = einsum('bhwk,bkc->bhwc', probs, palettes)
// gumbel = -log(-log(u+EPS)+EPS);  single pass (no max-subtract), out_c = (sum p*pal_c)/(sum p)
//
// R2: palette in smem, launch_bounds(256,6), __ldcs streams.
// R3: single-wave persistent grid (888 blocks = 148x6).
// R4: f32x2 packed FMAs, lg2-domain gexp, pointer strength reduction.
// R5: 4 pixels/warp-iteration, 8 lanes/pixel. Palette LDS becomes a 4-way
//     broadcast (conflict-free, 4x less crossbar traffic), butterfly 5->3 stages,
//     64B stores. Targets the L1tex bottleneck (75.6% busy) throttling DRAM.

#define KDIM 256
#define CDIM 4
#define EPSF 1e-20f
#define LN2F 0.69314718055994530942f
#define LOG2EF 1.44269504088896340736f

typedef unsigned long long u64;

__device__ __forceinline__ float lg2f(float x) {
    float r; asm("lg2.approx.f32 %0, %1;" : "=f"(r) : "f"(x)); return r;
}
__device__ __forceinline__ float ex2f(float x) {
    float r; asm("ex2.approx.f32 %0, %1;" : "=f"(r) : "f"(x)); return r;
}
__device__ __forceinline__ u64 pack2(float lo, float hi) {
    u64 r; asm("mov.b64 %0, {%1, %2};" : "=l"(r) : "f"(lo), "f"(hi)); return r;
}
__device__ __forceinline__ float2 unpack2(u64 v) {
    float2 r; asm("mov.b64 {%0, %1}, %2;" : "=f"(r.x), "=f"(r.y) : "l"(v)); return r;
}
__device__ __forceinline__ u64 fma2(u64 a, u64 b, u64 c) {
    u64 d; asm("fma.rn.f32x2 %0, %1, %2, %3;" : "=l"(d) : "l"(a), "l"(b), "l"(c)); return d;
}
__device__ __forceinline__ u64 add2(u64 a, u64 b) {
    u64 d; asm("add.rn.f32x2 %0, %1, %2;" : "=l"(d) : "l"(a), "l"(b)); return d;
}

// pe = exp((x - log(-log(u+eps)+eps)) * invT) in log2 domain.
__device__ __forceinline__ float gexp(float x, float u, float c1, float c2) {
    float t1 = lg2f(u + EPSF);
    float w  = fmaf(t1, -LN2F, EPSF);
    float t2 = lg2f(w);
    return ex2f(fmaf(x, c1, t2 * c2));
}

__global__ __launch_bounds__(256, 6)
void gsq_kernel(const float* __restrict__ images,
                const float* __restrict__ palettes,
                const float* __restrict__ noise,
                const float* __restrict__ temp,
                float* __restrict__ out,
                int hw)
{
    // Palette permuted for broadcast reads: entry k=(32j+4g+e) stored at
    // index (4j+e)*8+g, so for fixed (j,e) the 8 glane lanes read one
    // contiguous 128B block (conflict-free), 4-way broadcast across groups.
    __shared__ ulonglong2 spal[256];   // 4KB

    const int lane  = threadIdx.x & 31;
    const int glane = lane & 7;        // position within 8-lane pixel group
    const int grp   = lane >> 3;       // which of 4 pixels
    const int wid   = threadIdx.x >> 5;
    const int batch = blockIdx.y;
    const int warps_per_block = blockDim.x >> 5;
    const int warp_global = blockIdx.x * warps_per_block + wid;
    const int warp_stride = gridDim.x * warps_per_block;   // 888 warps per batch

    const float invT = __fdividef(1.0f, temp[0]);
    const float c1 = invT * LOG2EF;
    const float c2 = -invT;

    {
        const float4* __restrict__ pal =
            (const float4*)(palettes + (size_t)batch * KDIM * CDIM);
        int e = threadIdx.x;                       // entry k
        int dst = ((e >> 5) * 4 + (e & 3)) * 8 + ((e >> 2) & 7);
        ((float4*)spal)[dst] = pal[e];
    }
    __syncthreads();

    const size_t base_b = (size_t)batch * hw * KDIM;
    // This lane's pixel row (64 float4 per row), plus its glane offset.
    const float4* ip = (const float4*)(images + base_b)
                       + ((size_t)(warp_global * 4 + grp) << 6) + glane;
    const float4* np = (const float4*)(noise + base_b)
                       + ((size_t)(warp_global * 4 + grp) << 6) + glane;
    float4* outp = (float4*)out + (size_t)batch * hw + warp_global * 4;
    const size_t step = (size_t)warp_stride << 8;   // warp_stride*4 rows of 64 float4
    const int ostep = warp_stride * 4;

    for (int p = warp_global * 4; p < hw; p += warp_stride * 4,
                                          ip += step, np += step, outp += ostep) {
        u64 accA = 0, accB = 0, s2 = 0;

#pragma unroll
        for (int j = 0; j < 8; j += 2) {
            // 4 independent loads, each = 4 x 128B coalesced lines
            float4 a0 = __ldcs(ip + 8 * j);
            float4 a1 = __ldcs(ip + 8 * (j + 1));
            float4 n0 = __ldcs(np + 8 * j);
            float4 n1 = __ldcs(np + 8 * (j + 1));

            float pe0, pe1, pe2, pe3; u64 d; ulonglong2 P;

            pe0 = gexp(a0.x, n0.x, c1, c2);
            pe1 = gexp(a0.y, n0.y, c1, c2);
            pe2 = gexp(a0.z, n0.z, c1, c2);
            pe3 = gexp(a0.w, n0.w, c1, c2);
            s2 = add2(s2, pack2(pe0, pe1));
            s2 = add2(s2, pack2(pe2, pe3));
            P = spal[(4 * j + 0) * 8 + glane]; d = pack2(pe0, pe0);
            accA = fma2(d, P.x, accA); accB = fma2(d, P.y, accB);
            P = spal[(4 * j + 1) * 8 + glane]; d = pack2(pe1, pe1);
            accA = fma2(d, P.x, accA); accB = fma2(d, P.y, accB);
            P = spal[(4 * j + 2) * 8 + glane]; d = pack2(pe2, pe2);
            accA = fma2(d, P.x, accA); accB = fma2(d, P.y, accB);
            P = spal[(4 * j + 3) * 8 + glane]; d = pack2(pe3, pe3);
            accA = fma2(d, P.x, accA); accB = fma2(d, P.y, accB);

            pe0 = gexp(a1.x, n1.x, c1, c2);
            pe1 = gexp(a1.y, n1.y, c1, c2);
            pe2 = gexp(a1.z, n1.z, c1, c2);
            pe3 = gexp(a1.w, n1.w, c1, c2);
            s2 = add2(s2, pack2(pe0, pe1));
            s2 = add2(s2, pack2(pe2, pe3));
            P = spal[(4 * (j + 1) + 0) * 8 + glane]; d = pack2(pe0, pe0);
            accA = fma2(d, P.x, accA); accB = fma2(d, P.y, accB);
            P = spal[(4 * (j + 1) + 1) * 8 + glane]; d = pack2(pe1, pe1);
            accA = fma2(d, P.x, accA); accB = fma2(d, P.y, accB);
            P = spal[(4 * (j + 1) + 2) * 8 + glane]; d = pack2(pe2, pe2);
            accA = fma2(d, P.x, accA); accB = fma2(d, P.y, accB);
            P = spal[(4 * (j + 1) + 3) * 8 + glane]; d = pack2(pe3, pe3);
            accA = fma2(d, P.x, accA); accB = fma2(d, P.y, accB);
        }

        // 3-stage butterfly within each 8-lane group (xor of bits 0..2)
        float2 sp = unpack2(s2);
        float s = sp.x + sp.y;
#pragma unroll
        for (int off = 1; off < 8; off <<= 1) {
            s += __shfl_xor_sync(0xffffffffu, s, off);
            float2 ua = unpack2(accA);
            float2 ub = unpack2(accB);
            accA = add2(accA, pack2(__shfl_xor_sync(0xffffffffu, ua.x, off),
                                    __shfl_xor_sync(0xffffffffu, ua.y, off)));
            accB = add2(accB, pack2(__shfl_xor_sync(0xffffffffu, ub.x, off),
                                    __shfl_xor_sync(0xffffffffu, ub.y, off)));
        }

        if (glane == 0) {
            float inv = __fdividef(1.0f, s);
            float2 oa = unpack2(accA);
            float2 ob = unpack2(accB);
            float4 o;
            o.x = oa.x * inv; o.y = oa.y * inv;
            o.z = ob.x * inv; o.w = ob.y * inv;
            outp[grp] = o;   // lanes 0,8,16,24 -> contiguous 64B store
        }
    }
}

extern "C" void kernel_launch(void* const* d_in, const int* in_sizes, int n_in,
                              void* d_out, int out_size) {
    const float* images   = (const float*)d_in[0];
    const float* palettes = (const float*)d_in[1];
    const float* noise    = (const float*)d_in[2];
    const float* temp     = (const float*)d_in[3];
    float* out = (float*)d_out;

    int batches = in_sizes[1] / (KDIM * CDIM);               // 8
    int hw = (int)(in_sizes[0] / ((size_t)batches * KDIM));  // 65536

    dim3 block(256, 1, 1);
    // Single full wave: 148 SMs x 6 resident blocks = 888 blocks = 111 x 8 batches.
    dim3 grid(111, batches, 1);
    gsq_kernel<<<grid, block>>>(images, palettes, noise, temp, out, hw);
}